// round 17
// baseline (speedup 1.0000x reference)
#include <cuda_runtime.h>
#include <cuda_fp16.h>
#include <cstdint>
#include <cstddef>

// ---------------------------------------------------------------------------
// FeatureFusionKAN on GB300 (sm_103 non-'a' => legacy mma.sync only):
//   GEMM1 (K=2048):  logits = [f1|f2] @ attn_w^T   -> fused epilogue builds Xe0
//   GEMM2 (K=18432): h = Xe0 @ W0                  -> fused epilogue builds Xe1
//   GEMM3 (K=9216):  out = Xe1 @ W1
// FP16 mma.sync m16n8k16 (ldmatrix operand loads), fp32 accumulate.
// 128x128 CTA tile, 4 warps @ 64x64, BK=32 fp16, 3-stage cp.async pipeline.
// ---------------------------------------------------------------------------

#define BATCH   8192
#define FEATN   1024
#define KATTN   2048
#define KL0     18432
#define KL1     9216

// ------------------------- device scratch (no allocs) ----------------------
__device__ __half g_Acomb [(size_t)BATCH * KATTN];   //  32 MB
__device__ __half g_Wattn [(size_t)FEATN * KATTN];   //   4 MB
__device__ __half g_W0    [(size_t)FEATN * KL0];     //  36 MB
__device__ __half g_Xe0   [(size_t)BATCH * KL0];     // 288 MB
__device__ __half g_W1    [(size_t)FEATN * KL1];     //  18 MB
__device__ __half g_Xe1   [(size_t)BATCH * KL1];     // 144 MB

// ------------------------------ helpers ------------------------------------
__device__ __forceinline__ float sigmoidf_(float z) {
    return 1.0f / (1.0f + __expf(-z));
}

// Cox-de Boor, order 3, uniform extended grid g_j = -1 + (j-3)*0.4, j=0..11.
__device__ __forceinline__ void bspline8(float x, float bb[8]) {
    const float h = 0.4f;
    float b[11];
#pragma unroll
    for (int j = 0; j < 11; ++j) {
        float g0 = -1.0f + (float)(j - 3) * h;
        float g1 = -1.0f + (float)(j - 2) * h;
        b[j] = (x >= g0 && x < g1) ? 1.0f : 0.0f;
    }
#pragma unroll
    for (int k = 1; k <= 3; ++k) {
        float invkh = 1.0f / ((float)k * h);
#pragma unroll
        for (int j = 0; j < 11 - k; ++j) {
            float gj   = -1.0f + (float)(j - 3) * h;
            float gjk1 = -1.0f + (float)(j + k - 2) * h;
            float left  = (x - gj)   * invkh;
            float right = (gjk1 - x) * invkh;
            b[j] = left * b[j] + right * b[j + 1];
        }
    }
#pragma unroll
    for (int i = 0; i < 8; ++i) bb[i] = b[i];
}

__device__ __forceinline__ uint32_t h2u(float a, float b) {
    __half2 h = __halves2half2(__float2half_rn(a), __float2half_rn(b));
    return *reinterpret_cast<uint32_t*>(&h);
}

__device__ __forceinline__ void store_basis(__half* p, float x) {
    float bb[8];
    bspline8(x, bb);
    __align__(16) __half hb[8];
#pragma unroll
    for (int i = 0; i < 8; ++i) hb[i] = __float2half_rn(bb[i]);
    *reinterpret_cast<uint4*>(p) = *reinterpret_cast<const uint4*>(hb);
}

__device__ __forceinline__ void cvt8(const float4 u, const float4 v,
                                     uint4* dst) {
    __align__(16) __half hb[8];
    hb[0] = __float2half_rn(u.x); hb[1] = __float2half_rn(u.y);
    hb[2] = __float2half_rn(u.z); hb[3] = __float2half_rn(u.w);
    hb[4] = __float2half_rn(v.x); hb[5] = __float2half_rn(v.y);
    hb[6] = __float2half_rn(v.z); hb[7] = __float2half_rn(v.w);
    *dst = *reinterpret_cast<const uint4*>(hb);
}

// --------------------------- prep kernels (x8) ------------------------------
__global__ void k_concat_half8(const float* __restrict__ f1,
                               const float* __restrict__ f2,
                               __half* __restrict__ dst) {
    int idx = blockIdx.x * blockDim.x + threadIdx.x;
    if (idx >= BATCH * KATTN / 8) return;
    int e = idx * 8;
    int b = e >> 11;
    int j = e & 2047;
    const float* s = (j < FEATN) ? f1 + (size_t)b * FEATN + j
                                 : f2 + (size_t)b * FEATN + (j - FEATN);
    const float4* s4 = (const float4*)s;
    cvt8(s4[0], s4[1], (uint4*)dst + idx);
}

__global__ void k_half_copy8(const float* __restrict__ src,
                             __half* __restrict__ dst, int n8) {
    int idx = blockIdx.x * blockDim.x + threadIdx.x;
    if (idx >= n8) return;
    const float4* s4 = (const float4*)(src + idx * 8);
    cvt8(s4[0], s4[1], (uint4*)dst + idx);
}

__global__ void k_pack_w8(const float* __restrict__ basew,
                          const float* __restrict__ splinew,
                          __half* __restrict__ dst,
                          int kbase, int ktot) {
    int idx = blockIdx.x * blockDim.x + threadIdx.x;
    if (idx >= FEATN * ktot / 8) return;
    int e = idx * 8;
    int n = e / ktot;
    int k = e - n * ktot;
    const float* s = (k < kbase) ? basew + (size_t)n * kbase + k
                                 : splinew + (size_t)n * (ktot - kbase) + (k - kbase);
    const float4* s4 = (const float4*)s;
    cvt8(s4[0], s4[1], (uint4*)dst + idx);
}

// ------------------------------- GEMM --------------------------------------
// C[M,N] = A[M,K] (row-major fp16) * B^T, B stored [N][K] (K contiguous fp16).
// MODE 0: store float C. MODE 1: attention epilogue -> Xe0 (stride KL0).
// MODE 2: silu/bspline epilogue -> Xe1 (stride KL1).
#define GT_M     128
#define GT_N     128
#define GT_BK    32            // fp16 per K-chunk (64 bytes/row)
#define HSTRIDE  40            // fp16 per smem row (80 B)
#define GT_S     3             // pipeline stages
#define STG_H    (GT_M * HSTRIDE * 2)          // fp16 per stage (A+B) = 10240
#define GT_SMEM  (GT_S * STG_H * 2)            // 61440 bytes

__device__ __forceinline__ void cp_async16(void* smem, const void* gmem) {
    uint32_t s = (uint32_t)__cvta_generic_to_shared(smem);
    asm volatile("cp.async.cg.shared.global [%0], [%1], 16;\n" ::
                 "r"(s), "l"(gmem));
}

__device__ __forceinline__ void ldsm_x4(uint32_t r[4], uint32_t addr) {
    asm volatile(
        "ldmatrix.sync.aligned.m8n8.x4.shared.b16 {%0,%1,%2,%3}, [%4];"
        : "=r"(r[0]), "=r"(r[1]), "=r"(r[2]), "=r"(r[3]) : "r"(addr));
}

__device__ __forceinline__ void mma_f16(float c[4], const uint32_t a[4],
                                        uint32_t b0, uint32_t b1) {
    asm volatile(
        "mma.sync.aligned.m16n8k16.row.col.f32.f16.f16.f32 "
        "{%0,%1,%2,%3}, {%4,%5,%6,%7}, {%8,%9}, {%0,%1,%2,%3};\n"
        : "+f"(c[0]), "+f"(c[1]), "+f"(c[2]), "+f"(c[3])
        : "r"(a[0]), "r"(a[1]), "r"(a[2]), "r"(a[3]),
          "r"(b0), "r"(b1));
}

template <int MODE>
__global__ void __launch_bounds__(128, 2)
k_gemm(const __half* __restrict__ A, const __half* __restrict__ B,
       float* __restrict__ C, __half* __restrict__ XE,
       const float* __restrict__ f1, const float* __restrict__ f2,
       const float* __restrict__ bias, int M, int N, int K) {
    extern __shared__ __half Hs[];  // [GT_S][A:128*40 | B:128*40]

    const int tid  = threadIdx.x;
    const int lane = tid & 31;
    const int wid  = tid >> 5;
    const int wm   = wid & 1;   // warp row (0..1) -> 64 M-rows
    const int wn   = wid >> 1;  // warp col (0..1) -> 64 N-cols
    const int g    = lane >> 2;
    const int t4   = lane & 3;

    const int mBase = blockIdx.y * GT_M;
    const int nBase = blockIdx.x * GT_N;
    const int numK  = K / GT_BK;

    // ldmatrix per-lane byte offsets (within a stage)
    const uint32_t smB = (uint32_t)__cvta_generic_to_shared(Hs);
    const uint32_t aOff =
        (uint32_t)((wm * 64 + (lane & 15)) * HSTRIDE + ((lane >> 4) << 3)) * 2u;
    const uint32_t bOff =
        (uint32_t)(GT_M * HSTRIDE +
                   (wn * 64 + (lane & 7) + ((lane >> 4) << 3)) * HSTRIDE +
                   (((lane >> 3) & 1) << 3)) * 2u;

    // loader mapping: 128 thr x 4 row-passes x (A chunk + B chunk of 16B)
    const int ldRow = tid >> 2;          // 0..31 (then +32,+64,+96)
    const int ldC   = (tid & 3) * 8;     // fp16 offset: 0,8,16,24
    const __half* Aptr = A + (size_t)(mBase + ldRow) * K + ldC;
    const __half* Bptr = B + (size_t)(nBase + ldRow) * K + ldC;

    float acc[4][8][4];
#pragma unroll
    for (int mt = 0; mt < 4; ++mt)
#pragma unroll
        for (int nt = 0; nt < 8; ++nt)
#pragma unroll
            for (int i = 0; i < 4; ++i) acc[mt][nt][i] = 0.0f;

    // ---- prologue ----
#pragma unroll
    for (int t = 0; t < GT_S - 1; ++t) {
        __half* sa = Hs + t * STG_H;
        __half* sb = sa + GT_M * HSTRIDE;
        const size_t ko = (size_t)t * GT_BK;
#pragma unroll
        for (int i = 0; i < 4; ++i) {
            cp_async16(sa + (ldRow + 32 * i) * HSTRIDE + ldC,
                       Aptr + (size_t)(32 * i) * K + ko);
            cp_async16(sb + (ldRow + 32 * i) * HSTRIDE + ldC,
                       Bptr + (size_t)(32 * i) * K + ko);
        }
        asm volatile("cp.async.commit_group;\n");
    }

    int stC = 0;
    int stL = GT_S - 1;
    for (int kt = 0; kt < numK; ++kt) {
        asm volatile("cp.async.wait_group %0;\n" :: "n"(GT_S - 2));
        __syncthreads();

        // refill tile kt + GT_S - 1 into slot stL
        {
            int tl = kt + GT_S - 1;
            if (tl < numK) {
                __half* sa = Hs + stL * STG_H;
                __half* sb = sa + GT_M * HSTRIDE;
                const size_t ko = (size_t)tl * GT_BK;
#pragma unroll
                for (int i = 0; i < 4; ++i) {
                    cp_async16(sa + (ldRow + 32 * i) * HSTRIDE + ldC,
                               Aptr + (size_t)(32 * i) * K + ko);
                    cp_async16(sb + (ldRow + 32 * i) * HSTRIDE + ldC,
                               Bptr + (size_t)(32 * i) * K + ko);
                }
            }
            asm volatile("cp.async.commit_group;\n");
        }

        // compute on slot stC: 2 k-steps of k=16, operands via ldmatrix
        const uint32_t sBase = smB + (uint32_t)stC * (STG_H * 2);
#pragma unroll
        for (int ks = 0; ks < 2; ++ks) {
            const uint32_t kkb = (uint32_t)ks * 32;   // 16 halves
            uint32_t a[4][4];
#pragma unroll
            for (int mt = 0; mt < 4; ++mt)
                ldsm_x4(a[mt], sBase + aOff + (uint32_t)mt * (16 * HSTRIDE * 2) + kkb);
            uint32_t b[4][4];  // [np]: {nt=2np k0, 2np k1, 2np+1 k0, 2np+1 k1}
#pragma unroll
            for (int np = 0; np < 4; ++np)
                ldsm_x4(b[np], sBase + bOff + (uint32_t)np * (16 * HSTRIDE * 2) + kkb);
#pragma unroll
            for (int mt = 0; mt < 4; ++mt)
#pragma unroll
                for (int nt = 0; nt < 8; ++nt) {
                    const int np = nt >> 1, i0 = (nt & 1) * 2;
                    mma_f16(acc[mt][nt], a[mt], b[np][i0], b[np][i0 + 1]);
                }
        }

        if (++stC == GT_S) stC = 0;
        if (++stL == GT_S) stL = 0;
    }

    // ---- epilogue ----
#pragma unroll
    for (int mt = 0; mt < 4; ++mt) {
#pragma unroll
        for (int nt = 0; nt < 8; ++nt) {
            const int r0 = mBase + wm * 64 + mt * 16 + g;
            const int c  = nBase + wn * 64 + nt * 8 + 2 * t4;
#pragma unroll
            for (int rr = 0; rr < 2; ++rr) {
                const int r = r0 + 8 * rr;
                const float v0 = acc[mt][nt][2 * rr + 0];
                const float v1 = acc[mt][nt][2 * rr + 1];
                if (MODE == 0) {
                    *(float2*)(C + (size_t)r * N + c) = make_float2(v0, v1);
                } else if (MODE == 1) {
                    // attention -> kan_in -> silu + bspline into Xe0
                    float2 F1 = *(const float2*)(f1 + (size_t)r * FEATN + c);
                    float2 F2 = *(const float2*)(f2 + (size_t)r * FEATN + c);
                    float a0 = sigmoidf_(v0 + bias[c]);
                    float a1 = sigmoidf_(v1 + bias[c + 1]);
                    float x10 = F1.x * a0,          x11 = F1.y * a1;
                    float x20 = F2.x * (1.0f - a0), x21 = F2.y * (1.0f - a1);
                    __half* row = XE + (size_t)r * KL0;
                    *(uint32_t*)(row + c) =
                        h2u(x10 * sigmoidf_(x10), x11 * sigmoidf_(x11));
                    *(uint32_t*)(row + FEATN + c) =
                        h2u(x20 * sigmoidf_(x20), x21 * sigmoidf_(x21));
                    store_basis(row + KATTN + 8 * (size_t)c,          x10);
                    store_basis(row + KATTN + 8 * (size_t)(c + 1),    x11);
                    store_basis(row + KATTN + 8 * (size_t)(c + 1024), x20);
                    store_basis(row + KATTN + 8 * (size_t)(c + 1025), x21);
                } else {
                    // h -> silu + bspline into Xe1
                    __half* row = XE + (size_t)r * KL1;
                    *(uint32_t*)(row + c) =
                        h2u(v0 * sigmoidf_(v0), v1 * sigmoidf_(v1));
                    store_basis(row + FEATN + 8 * (size_t)c,       v0);
                    store_basis(row + FEATN + 8 * (size_t)(c + 1), v1);
                }
            }
        }
    }
}

// ------------------------------ launch --------------------------------------
extern "C" void kernel_launch(void* const* d_in, const int* in_sizes, int n_in,
                              void* d_out, int out_size) {
    const float* feat1     = (const float*)d_in[0];
    const float* feat2     = (const float*)d_in[1];
    const float* attn_w    = (const float*)d_in[2];
    const float* attn_b    = (const float*)d_in[3];
    const float* base_w0   = (const float*)d_in[4];
    const float* spline_w0 = (const float*)d_in[5];
    const float* base_w1   = (const float*)d_in[6];
    const float* spline_w1 = (const float*)d_in[7];
    float* out = (float*)d_out;

    __half *Acomb, *Wattn, *W0, *Xe0, *W1, *Xe1;
    cudaGetSymbolAddress((void**)&Acomb, g_Acomb);
    cudaGetSymbolAddress((void**)&Wattn, g_Wattn);
    cudaGetSymbolAddress((void**)&W0,    g_W0);
    cudaGetSymbolAddress((void**)&Xe0,   g_Xe0);
    cudaGetSymbolAddress((void**)&W1,    g_W1);
    cudaGetSymbolAddress((void**)&Xe1,   g_Xe1);

    cudaFuncSetAttribute(k_gemm<0>,
                         cudaFuncAttributeMaxDynamicSharedMemorySize, GT_SMEM);
    cudaFuncSetAttribute(k_gemm<1>,
                         cudaFuncAttributeMaxDynamicSharedMemorySize, GT_SMEM);
    cudaFuncSetAttribute(k_gemm<2>,
                         cudaFuncAttributeMaxDynamicSharedMemorySize, GT_SMEM);

    const dim3 gemmGrid(FEATN / GT_N, BATCH / GT_M);  // (8, 64)

    // weight prep (independent of activations)
    {
        int n8 = FEATN * KATTN / 8;
        k_half_copy8<<<(n8 + 255) / 256, 256>>>(attn_w, Wattn, n8);
    }
    {
        int n8 = FEATN * KL0 / 8;
        k_pack_w8<<<(n8 + 255) / 256, 256>>>(base_w0, spline_w0, W0, KATTN, KL0);
    }
    {
        int n8 = FEATN * KL1 / 8;
        k_pack_w8<<<(n8 + 255) / 256, 256>>>(base_w1, spline_w1, W1, FEATN, KL1);
    }

    // attention GEMM A operand
    {
        int n8 = BATCH * KATTN / 8;
        k_concat_half8<<<(n8 + 255) / 256, 256>>>(feat1, feat2, Acomb);
    }

    // GEMM1 + fused attention/expansion epilogue -> Xe0
    k_gemm<1><<<gemmGrid, 128, GT_SMEM>>>(Acomb, Wattn, nullptr, Xe0,
                                          feat1, feat2, attn_b,
                                          BATCH, FEATN, KATTN);

    // GEMM2 + fused silu/bspline epilogue -> Xe1
    k_gemm<2><<<gemmGrid, 128, GT_SMEM>>>(Xe0, W0, nullptr, Xe1,
                                          nullptr, nullptr, nullptr,
                                          BATCH, FEATN, KL0);

    // GEMM3 -> out
    k_gemm<0><<<gemmGrid, 128, GT_SMEM>>>(Xe1, W1, out, nullptr,
                                          nullptr, nullptr, nullptr,
                                          BATCH, FEATN, KL1);
}